// round 5
// baseline (speedup 1.0000x reference)
#include <cuda_runtime.h>
#include <math.h>

#define BATCH 256
#define D_IN  2048
#define HID   2048
#define NSEG  10
#define D_CTX 1024
#define OUT_N 100
#define KWIN  102
#define NDEND (HID * NSEG)   /* 20480 */

#define SLOTS_D 112   /* dendrite rows: Binom(1024,.05) mean 51.2, sd 7.0 */
#define SLOTS_F 176   /* FF rows: Binom(2048,.05) mean 102.4, sd 9.9      */

/* ---------------- scratch (no allocations allowed) ---------------- */
__device__ float  g_CT [(size_t)D_CTX * BATCH];     /* ctx^T [1024][256] */
__device__ float  g_XT [(size_t)D_IN  * BATCH];     /* x^T   [2048][256] */
__device__ float  g_Yt [(size_t)HID   * BATCH];     /* FF preact [u][b]  */
__device__ float  g_V  [(size_t)BATCH * HID];       /* gated [b][u]      */
__device__ float  g_H  [(size_t)BATCH * HID];       /* kwin   [b][u]     */
__device__ float  g_HT [(size_t)HID   * BATCH];     /* kwin   [u][b]     */

__device__ float2 g_dp1[(size_t)NDEND * SLOTS_D];
__device__ int    g_dc1[NDEND];
__device__ float2 g_dp2[(size_t)NDEND * SLOTS_D];
__device__ int    g_dc2[NDEND];
__device__ float2 g_fp1[(size_t)HID * SLOTS_F];
__device__ int    g_fc1[HID];
__device__ float2 g_fp2[(size_t)HID * SLOTS_F];
__device__ int    g_fc2[HID];

/* ------------------------------------------------------------------
 * 32x32 tiled transpose: out[c][r] = in[r][c], in is rows x cols.
 * ------------------------------------------------------------------ */
__global__ __launch_bounds__(256)
void transpose_k(const float* __restrict__ in, float* __restrict__ out,
                 int rows, int cols)
{
    __shared__ float t[32][33];
    const int cb = blockIdx.x * 32, rb = blockIdx.y * 32;
    const int tx = threadIdx.x, ty = threadIdx.y;  /* 32 x 8 */
#pragma unroll
    for (int i = 0; i < 32; i += 8)
        t[ty + i][tx] = in[(size_t)(rb + ty + i) * cols + cb + tx];
    __syncthreads();
#pragma unroll
    for (int i = 0; i < 32; i += 8)
        out[(size_t)(cb + ty + i) * rows + rb + tx] = t[tx][ty + i];
}

/* ------------------------------------------------------------------
 * Compaction: one warp per weight row, ballot loop unrolled x4 for
 * MLP. Emits (val, byteoffset) pairs; offset premultiplied by the
 * consumer's smem row stride. Pads count to a multiple of 4 with
 * zero pairs (offset 0 -> harmless read of sA[0] * 0).
 * ------------------------------------------------------------------ */
template<int SLOTS>
__global__ __launch_bounds__(256)
void compact_k(const float* __restrict__ W, const float* __restrict__ M,
               float2* __restrict__ pairs, int* __restrict__ cnt,
               int R, int K, int mult)
{
    const int row = blockIdx.x * 8 + (threadIdx.x >> 5);
    if (row >= R) return;
    const int lane = threadIdx.x & 31;
    const unsigned lm = (1u << lane) - 1u;
    const float* mr = M + (size_t)row * K;
    const float* wr = W + (size_t)row * K;
    float2* po = pairs + (size_t)row * SLOTS;

    int base = 0;
    for (int c0 = 0; c0 < K; c0 += 128) {
        const float m0 = mr[c0      + lane];
        const float m1 = mr[c0 + 32 + lane];
        const float m2 = mr[c0 + 64 + lane];
        const float m3 = mr[c0 + 96 + lane];
        const unsigned x0 = __ballot_sync(0xffffffffu, m0 != 0.f);
        const unsigned x1 = __ballot_sync(0xffffffffu, m1 != 0.f);
        const unsigned x2 = __ballot_sync(0xffffffffu, m2 != 0.f);
        const unsigned x3 = __ballot_sync(0xffffffffu, m3 != 0.f);
        if (m0 != 0.f) {
            const int p = base + __popc(x0 & lm);
            if (p < SLOTS) po[p] = make_float2(wr[c0 + lane],
                                   __int_as_float((c0 + lane) * mult));
        }
        base += __popc(x0);
        if (m1 != 0.f) {
            const int p = base + __popc(x1 & lm);
            if (p < SLOTS) po[p] = make_float2(wr[c0 + 32 + lane],
                                   __int_as_float((c0 + 32 + lane) * mult));
        }
        base += __popc(x1);
        if (m2 != 0.f) {
            const int p = base + __popc(x2 & lm);
            if (p < SLOTS) po[p] = make_float2(wr[c0 + 64 + lane],
                                   __int_as_float((c0 + 64 + lane) * mult));
        }
        base += __popc(x2);
        if (m3 != 0.f) {
            const int p = base + __popc(x3 & lm);
            if (p < SLOTS) po[p] = make_float2(wr[c0 + 96 + lane],
                                   __int_as_float((c0 + 96 + lane) * mult));
        }
        base += __popc(x3);
    }
    if (base > SLOTS) base = SLOTS;
    const int padded = (base + 3) & ~3;
    if (lane < padded - base) po[base + lane] = make_float2(0.f, __int_as_float(0));
    if (lane == 0) cnt[row] = padded;
}

/* ------------------------------------------------------------------
 * FF sparse GEMM, BSUB=16: Yt[n][b] = sum_j val * AT[idx][b].
 * sA = AT chunk [2048][17] (pad 17 vs bank conflicts). Pair stream
 * read via broadcast LDG.128; lane halves split pair parity.
 * ------------------------------------------------------------------ */
__global__ __launch_bounds__(256)
void ff_mm(const float* __restrict__ AT, const float2* __restrict__ pairs,
           const int* __restrict__ cnt, float* __restrict__ Yt,
           int rows_per_blk)
{
    extern __shared__ __align__(16) char smem[];
    float* sA = (float*)smem;                       /* [2048][17] */
    const int tid = threadIdx.x, w = tid >> 5, lane = tid & 31;
    const int bl = lane & 15, half = lane >> 4;
    const int b0 = blockIdx.x * 16;

    for (int i = tid; i < D_IN * 4; i += 256) {
        const int k = i >> 2, q = (i & 3) * 4;
        const float4 v = *(const float4*)(AT + (size_t)k * BATCH + b0 + q);
        float* d = sA + k * 17 + q;
        d[0] = v.x; d[1] = v.y; d[2] = v.z; d[3] = v.w;
    }
    __syncthreads();

    const char* lptr = (const char*)smem + bl * 4;
    const int r0 = blockIdx.y * rows_per_blk;
    int r1 = r0 + rows_per_blk; if (r1 > HID) r1 = HID;

    for (int n = r0 + w; n < r1; n += 8) {
        const int c = cnt[n];
        const float2* p = pairs + (size_t)n * SLOTS_F;
        float a0 = 0.f, a1 = 0.f;
        for (int j = 0; j < c; j += 4) {
            const float4 q0 = *(const float4*)(p + j);
            const float4 q1 = *(const float4*)(p + j + 2);
            const float v0 = half ? q0.z : q0.x;
            const int   o0 = __float_as_int(half ? q0.w : q0.y);
            const float v1 = half ? q1.z : q1.x;
            const int   o1 = __float_as_int(half ? q1.w : q1.y);
            a0 = fmaf(*(const float*)(lptr + o0), v0, a0);
            a1 = fmaf(*(const float*)(lptr + o1), v1, a1);
        }
        float acc = a0 + a1;
        acc += __shfl_xor_sync(0xffffffffu, acc, 16);
        if (half == 0) Yt[(size_t)n * BATCH + b0 + bl] = acc;
    }
}

/* ------------------------------------------------------------------
 * Fused dendrite GEMM + abs-argmax + sigmoid gate. BSUB=32.
 * sA = CT chunk [1024][32] (stride 32 -> conflict-free gather).
 * Each warp: 16 consecutive units x 10 segments, pair stream via
 * broadcast LDG.128. Gated values staged in an smem tile so V is
 * written coalesced in [b][u] layout.
 * ------------------------------------------------------------------ */
__global__ __launch_bounds__(256)
void dend_gate(const float* __restrict__ CT, const float2* __restrict__ pairs,
               const int* __restrict__ cnt, const float* __restrict__ Yt,
               const float* __restrict__ bias, float* __restrict__ V)
{
    extern __shared__ __align__(16) char smem[];
    float* sA   = (float*)smem;                          /* [1024][32] */
    float* tile = (float*)(smem + (size_t)D_CTX * 32 * 4); /* [128][33] */
    const int tid = threadIdx.x, w = tid >> 5, lane = tid & 31;
    const int b0 = blockIdx.x * 32, u0 = blockIdx.y * 128;

    for (int i = tid; i < D_CTX * 8; i += 256) {
        const int k = i >> 3, q = (i & 7) * 4;
        const float4 v = *(const float4*)(CT + (size_t)k * BATCH + b0 + q);
        *(float4*)(sA + k * 32 + q) = v;
    }
    __syncthreads();

    const char* lptr = (const char*)smem + lane * 4;

#pragma unroll 1
    for (int i = 0; i < 16; i++) {
        const int ul = w * 16 + i;
        const int u  = u0 + ul;
        float best = 0.f, besta = -1.f;
#pragma unroll 1
        for (int s = 0; s < NSEG; s++) {
            const int row = u * NSEG + s;
            const int c = cnt[row];
            const float2* p = pairs + (size_t)row * SLOTS_D;
            float a0 = 0.f, a1 = 0.f, a2 = 0.f, a3 = 0.f;
            for (int j = 0; j < c; j += 4) {
                const float4 q0 = *(const float4*)(p + j);
                const float4 q1 = *(const float4*)(p + j + 2);
                a0 = fmaf(*(const float*)(lptr + __float_as_int(q0.y)), q0.x, a0);
                a1 = fmaf(*(const float*)(lptr + __float_as_int(q0.w)), q0.z, a1);
                a2 = fmaf(*(const float*)(lptr + __float_as_int(q1.y)), q1.x, a2);
                a3 = fmaf(*(const float*)(lptr + __float_as_int(q1.w)), q1.z, a3);
            }
            const float acc = (a0 + a1) + (a2 + a3);
            const float aa = fabsf(acc);
            if (aa > besta) { besta = aa; best = acc; }   /* first max */
        }
        const float y = Yt[(size_t)u * BATCH + b0 + lane] + bias[u];
        const float gate = 1.f / (1.f + expf(-best));
        tile[ul * 33 + lane] = y * gate;
    }
    __syncthreads();

    for (int i = tid; i < 128 * 32; i += 256) {
        const int uu = i & 127, bb = i >> 7;
        V[(size_t)(b0 + bb) * HID + u0 + uu] = tile[uu * 33 + bb];
    }
}

/* ------------------------------------------------------------------
 * Exact top-K per batch row. Keys/values live in registers (8 per
 * thread); per-bit counters in a small smem array -> 1 sync/round.
 * ------------------------------------------------------------------ */
__global__ __launch_bounds__(256)
void topk_k(const float* __restrict__ V, float* __restrict__ H)
{
    const int b = blockIdx.x, tid = threadIdx.x;
    __shared__ int scnt[32];
    if (tid < 32) scnt[tid] = 0;

    float v[8]; unsigned key[8];
#pragma unroll
    for (int e = 0; e < 8; e++) {
        const float x = V[(size_t)b * HID + e * 256 + tid];
        v[e] = x;
        const unsigned ui = __float_as_uint(x);
        key[e] = (ui & 0x80000000u) ? ~ui : (ui | 0x80000000u);
    }
    __syncthreads();

    unsigned T = 0u;
    for (int bit = 31; bit >= 0; bit--) {
        const unsigned cand = T | (1u << bit);
        int c = 0;
#pragma unroll
        for (int e = 0; e < 8; e++) c += (key[e] >= cand) ? 1 : 0;
        for (int o = 16; o; o >>= 1) c += __shfl_down_sync(0xffffffffu, c, o);
        if ((tid & 31) == 0) atomicAdd(&scnt[bit], c);
        __syncthreads();
        if (scnt[bit] >= KWIN) T = cand;
    }

#pragma unroll
    for (int e = 0; e < 8; e++)
        H[(size_t)b * HID + e * 256 + tid] = (key[e] >= T) ? v[e] : 0.f;
}

/* ------------------------------------------------------------------
 * Dale head: out[b,o] = dot(h, Wex[o]) - Wei[o]*dot(h, Wix) + b_out[o]
 * ------------------------------------------------------------------ */
__global__ __launch_bounds__(128)
void head_k(const float* __restrict__ H,
            const float* __restrict__ Wex, const float* __restrict__ Wix,
            const float* __restrict__ Wei, const float* __restrict__ bo,
            float* __restrict__ out)
{
    const int b = blockIdx.x, tid = threadIdx.x;
    __shared__ __align__(16) float sh[HID];
    __shared__ float sred[4];

    for (int k = tid; k < HID; k += 128) sh[k] = H[(size_t)b * HID + k];
    __syncthreads();

    float p = 0.f;
    for (int k = tid; k < HID; k += 128) p += sh[k] * Wix[k];
    for (int o = 16; o; o >>= 1) p += __shfl_down_sync(0xffffffffu, p, o);
    if ((tid & 31) == 0) sred[tid >> 5] = p;
    __syncthreads();
    const float S = sred[0] + sred[1] + sred[2] + sred[3];

    if (tid < OUT_N) {
        const float* wrow = Wex + (size_t)tid * HID;
        float acc = 0.f;
#pragma unroll 4
        for (int k = 0; k < HID; k += 4) {
            const float4 wq = *(const float4*)(wrow + k);
            acc = fmaf(sh[k + 0], wq.x, acc);
            acc = fmaf(sh[k + 1], wq.y, acc);
            acc = fmaf(sh[k + 2], wq.z, acc);
            acc = fmaf(sh[k + 3], wq.w, acc);
        }
        out[(size_t)b * OUT_N + tid] = acc - Wei[tid] * S + bo[tid];
    }
}

/* ------------------------------------------------------------------ */
extern "C" void kernel_launch(void* const* d_in, const int* in_sizes, int n_in,
                              void* d_out, int out_size)
{
    (void)in_sizes; (void)n_in; (void)out_size;
    const float* x      = (const float*)d_in[0];
    const float* ctx    = (const float*)d_in[1];
    const float* W1     = (const float*)d_in[2];
    const float* b1     = (const float*)d_in[3];
    const float* segW1  = (const float*)d_in[4];
    const float* maskW1 = (const float*)d_in[5];
    const float* maskS1 = (const float*)d_in[6];
    const float* W2     = (const float*)d_in[7];
    const float* b2     = (const float*)d_in[8];
    const float* segW2  = (const float*)d_in[9];
    const float* maskW2 = (const float*)d_in[10];
    const float* maskS2 = (const float*)d_in[11];
    const float* Wex    = (const float*)d_in[12];
    const float* Wix    = (const float*)d_in[13];
    const float* Wei    = (const float*)d_in[14];
    const float* bo     = (const float*)d_in[15];
    float* out = (float*)d_out;

    float *pCT, *pXT, *pYt, *pV, *pH, *pHT;
    cudaGetSymbolAddress((void**)&pCT, g_CT);
    cudaGetSymbolAddress((void**)&pXT, g_XT);
    cudaGetSymbolAddress((void**)&pYt, g_Yt);
    cudaGetSymbolAddress((void**)&pV,  g_V);
    cudaGetSymbolAddress((void**)&pH,  g_H);
    cudaGetSymbolAddress((void**)&pHT, g_HT);

    float2 *dp1, *dp2, *fp1, *fp2;
    int *dc1, *dc2, *fc1, *fc2;
    cudaGetSymbolAddress((void**)&dp1, g_dp1); cudaGetSymbolAddress((void**)&dc1, g_dc1);
    cudaGetSymbolAddress((void**)&dp2, g_dp2); cudaGetSymbolAddress((void**)&dc2, g_dc2);
    cudaGetSymbolAddress((void**)&fp1, g_fp1); cudaGetSymbolAddress((void**)&fc1, g_fc1);
    cudaGetSymbolAddress((void**)&fp2, g_fp2); cudaGetSymbolAddress((void**)&fc2, g_fc2);

    const int smemF = D_IN * 17 * 4;                     /* 139264 */
    const int smemD = D_CTX * 32 * 4 + 128 * 33 * 4;     /* 131072 + 16896 */
    static int attr_done = 0;
    if (!attr_done) {
        cudaFuncSetAttribute((const void*)ff_mm,
                             cudaFuncAttributeMaxDynamicSharedMemorySize, smemF);
        cudaFuncSetAttribute((const void*)dend_gate,
                             cudaFuncAttributeMaxDynamicSharedMemorySize, smemD);
        attr_done = 1;
    }

    /* transposes of activations */
    transpose_k<<<dim3(D_CTX / 32, BATCH / 32), dim3(32, 8)>>>(ctx, pCT, BATCH, D_CTX);
    transpose_k<<<dim3(D_IN  / 32, BATCH / 32), dim3(32, 8)>>>(x,   pXT, BATCH, D_IN);

    /* weight compaction (95% sparse). offsets premultiplied:
       dendrite consumer stride 32 floats -> x128; FF stride 17 -> x68 */
    compact_k<SLOTS_D><<<NDEND / 8, 256>>>(segW1, maskS1, dp1, dc1, NDEND, D_CTX, 128);
    compact_k<SLOTS_D><<<NDEND / 8, 256>>>(segW2, maskS2, dp2, dc2, NDEND, D_CTX, 128);
    compact_k<SLOTS_F><<<HID / 8,   256>>>(W1,    maskW1, fp1, fc1, HID, D_IN, 68);
    compact_k<SLOTS_F><<<HID / 8,   256>>>(W2,    maskW2, fp2, fc2, HID, HID,  68);

    const int rpbF = (HID + 8) / 9;   /* 228 */

    /* layer 1 */
    ff_mm<<<dim3(16, 9), 256, smemF>>>(pXT, fp1, fc1, pYt, rpbF);
    dend_gate<<<dim3(8, 16), 256, smemD>>>(pCT, dp1, dc1, pYt, b1, pV);
    topk_k<<<BATCH, 256>>>(pV, pH);
    transpose_k<<<dim3(HID / 32, BATCH / 32), dim3(32, 8)>>>(pH, pHT, BATCH, HID);

    /* layer 2 */
    ff_mm<<<dim3(16, 9), 256, smemF>>>(pHT, fp2, fc2, pYt, rpbF);
    dend_gate<<<dim3(8, 16), 256, smemD>>>(pCT, dp2, dc2, pYt, b2, pV);
    topk_k<<<BATCH, 256>>>(pV, pH);

    /* Dale output head */
    head_k<<<BATCH, 128>>>(pH, Wex, Wix, Wei, bo, out);
}

// round 7
// speedup vs baseline: 2.0076x; 2.0076x over previous
#include <cuda_runtime.h>
#include <math.h>

#define BATCH 256
#define D_IN  2048
#define HID   2048
#define NSEG  10
#define D_CTX 1024
#define OUT_N 100
#define KWIN  102
#define NDEND (HID * NSEG)   /* 20480 */

#define SLOTS_D 112   /* dendrite rows: Binom(1024,.05) mean 51.2 sd 7.0, mult of 8 */
#define SLOTS_F 176   /* FF rows: Binom(2048,.05) mean 102.4 sd 9.9,  mult of 8 */

/* ---------------- scratch (no allocations allowed) ---------------- */
__device__ float  g_CT [(size_t)D_CTX * BATCH];
__device__ float  g_XT [(size_t)D_IN  * BATCH];
__device__ float  g_Yt [(size_t)HID   * BATCH];
__device__ float  g_V  [(size_t)BATCH * HID];
__device__ float  g_H  [(size_t)BATCH * HID];
__device__ float  g_HT [(size_t)HID   * BATCH];

__device__ float2 g_dp1[(size_t)NDEND * SLOTS_D];
__device__ int    g_dc1[NDEND];
__device__ float2 g_dp2[(size_t)NDEND * SLOTS_D];
__device__ int    g_dc2[NDEND];
__device__ float2 g_fp1[(size_t)HID * SLOTS_F];
__device__ int    g_fc1[HID];
__device__ float2 g_fp2[(size_t)HID * SLOTS_F];
__device__ int    g_fc2[HID];

/* ------------------------------------------------------------------ */
__global__ __launch_bounds__(256)
void transpose_k(const float* __restrict__ in, float* __restrict__ out,
                 int rows, int cols)
{
    __shared__ float t[32][33];
    const int cb = blockIdx.x * 32, rb = blockIdx.y * 32;
    const int tx = threadIdx.x, ty = threadIdx.y;  /* 32 x 8 */
#pragma unroll
    for (int i = 0; i < 32; i += 8)
        t[ty + i][tx] = in[(size_t)(rb + ty + i) * cols + cb + tx];
    __syncthreads();
#pragma unroll
    for (int i = 0; i < 32; i += 8)
        out[(size_t)(cb + ty + i) * rows + rb + tx] = t[tx][ty + i];
}

/* ------------------------------------------------------------------
 * Compaction: each warp handles 4 rows interleaved (4 independent
 * ballot chains, 8 mask loads in flight via double buffering).
 * Emits (val, premultiplied byte-offset) pairs, count padded to a
 * multiple of 8 with zero pairs (offset 0 -> harmless).
 * ------------------------------------------------------------------ */
template<int SLOTS>
__global__ __launch_bounds__(256)
void compact_k(const float* __restrict__ W, const float* __restrict__ M,
               float2* __restrict__ pairs, int* __restrict__ cnt,
               int R, int K, int mult)
{
    const int w    = threadIdx.x >> 5;
    const int lane = threadIdx.x & 31;
    const int row0 = (blockIdx.x * 8 + w) * 4;
    if (row0 >= R) return;
    const unsigned lm = (1u << lane) - 1u;

    int base[4] = {0, 0, 0, 0};
    float m[4], nm[4];
#pragma unroll
    for (int r = 0; r < 4; r++) m[r] = M[(size_t)(row0 + r) * K + lane];

    for (int c0 = 0; c0 < K; c0 += 32) {
        const int c1 = c0 + 32;
        if (c1 < K) {
#pragma unroll
            for (int r = 0; r < 4; r++)
                nm[r] = M[(size_t)(row0 + r) * K + c1 + lane];
        }
#pragma unroll
        for (int r = 0; r < 4; r++) {
            const unsigned bal = __ballot_sync(0xffffffffu, m[r] != 0.f);
            if (m[r] != 0.f) {
                const int p = base[r] + __popc(bal & lm);
                if (p < SLOTS)
                    pairs[(size_t)(row0 + r) * SLOTS + p] =
                        make_float2(W[(size_t)(row0 + r) * K + c0 + lane],
                                    __int_as_float((c0 + lane) * mult));
            }
            base[r] += __popc(bal);
        }
#pragma unroll
        for (int r = 0; r < 4; r++) m[r] = nm[r];
    }
#pragma unroll
    for (int r = 0; r < 4; r++) {
        int b = base[r] > SLOTS ? SLOTS : base[r];
        int padded = (b + 7) & ~7;
        if (padded > SLOTS) padded = SLOTS;
        if (lane < padded - b)
            pairs[(size_t)(row0 + r) * SLOTS + b + lane] =
                make_float2(0.f, __int_as_float(0));
        if (lane == 0) cnt[row0 + r] = padded;
    }
}

#define GATHER(off) (*(const float*)(lptr + __float_as_int(off)))

/* ------------------------------------------------------------------
 * Fused dendrite GEMM + abs-argmax + sigmoid gate.  BSUB=32.
 * 512 threads (16 warps). sA = CT chunk [1024][32] -> stride-32
 * conflict-free gather. Pair stream via broadcast LDG.128, software-
 * pipelined (prefetch next 4 float4 while computing current 8 nz).
 * ------------------------------------------------------------------ */
__global__ __launch_bounds__(512)
void dend_gate(const float* __restrict__ CT, const float2* __restrict__ pairs,
               const int* __restrict__ cnt, const float* __restrict__ Yt,
               const float* __restrict__ bias, float* __restrict__ V)
{
    extern __shared__ __align__(16) char smem[];
    float* sA   = (float*)smem;                              /* [1024][32] */
    float* tile = (float*)(smem + (size_t)D_CTX * 32 * 4);   /* [128][33]  */
    const int tid = threadIdx.x, w = tid >> 5, lane = tid & 31;
    const int b0 = blockIdx.x * 32, u0 = blockIdx.y * 128;

    for (int i = tid; i < D_CTX * 8; i += 512) {
        const int k = i >> 3, q = (i & 7) * 4;
        *(float4*)(sA + k * 32 + q) =
            *(const float4*)(CT + (size_t)k * BATCH + b0 + q);
    }
    __syncthreads();
    const char* lptr = (const char*)smem + lane * 4;

#pragma unroll 1
    for (int i = 0; i < 8; i++) {
        const int ul = w * 8 + i, u = u0 + ul;
        float best = 0.f, besta = -1.f;
#pragma unroll 1
        for (int s = 0; s < NSEG; s++) {
            const int row = u * NSEG + s;
            const int c4  = cnt[row] >> 1;    /* float4 count, mult of 4 */
            const float4* p4 = (const float4*)(pairs + (size_t)row * SLOTS_D);
            float a0 = 0.f, a1 = 0.f, a2 = 0.f, a3 = 0.f;
            if (c4) {
                float4 A = p4[0], B = p4[1], C = p4[2], D = p4[3];
#pragma unroll 1
                for (int j = 4; j < c4; j += 4) {
                    const float4 nA = p4[j],     nB = p4[j + 1];
                    const float4 nC = p4[j + 2], nD = p4[j + 3];
                    a0 = fmaf(GATHER(A.y), A.x, a0);
                    a0 = fmaf(GATHER(A.w), A.z, a0);
                    a1 = fmaf(GATHER(B.y), B.x, a1);
                    a1 = fmaf(GATHER(B.w), B.z, a1);
                    a2 = fmaf(GATHER(C.y), C.x, a2);
                    a2 = fmaf(GATHER(C.w), C.z, a2);
                    a3 = fmaf(GATHER(D.y), D.x, a3);
                    a3 = fmaf(GATHER(D.w), D.z, a3);
                    A = nA; B = nB; C = nC; D = nD;
                }
                a0 = fmaf(GATHER(A.y), A.x, a0);
                a0 = fmaf(GATHER(A.w), A.z, a0);
                a1 = fmaf(GATHER(B.y), B.x, a1);
                a1 = fmaf(GATHER(B.w), B.z, a1);
                a2 = fmaf(GATHER(C.y), C.x, a2);
                a2 = fmaf(GATHER(C.w), C.z, a2);
                a3 = fmaf(GATHER(D.y), D.x, a3);
                a3 = fmaf(GATHER(D.w), D.z, a3);
            }
            const float acc = (a0 + a1) + (a2 + a3);
            const float aa = fabsf(acc);
            if (aa > besta) { besta = aa; best = acc; }   /* first max */
        }
        const float y = Yt[(size_t)u * BATCH + b0 + lane] + bias[u];
        tile[ul * 33 + lane] = y * (1.f / (1.f + expf(-best)));
    }
    __syncthreads();

    for (int i = tid; i < 128 * 32; i += 512) {
        const int uu = i & 127, bb = i >> 7;
        V[(size_t)(b0 + bb) * HID + u0 + uu] = tile[uu * 33 + bb];
    }
}

/* ------------------------------------------------------------------
 * FF sparse GEMM, BSUB=16 half-split, 512 threads, same pipelining.
 * sA = AT chunk [2048][17].
 * ------------------------------------------------------------------ */
__global__ __launch_bounds__(512)
void ff_mm(const float* __restrict__ AT, const float2* __restrict__ pairs,
           const int* __restrict__ cnt, float* __restrict__ Yt,
           int rows_per_blk)
{
    extern __shared__ __align__(16) char smem[];
    float* sA = (float*)smem;                       /* [2048][17] */
    const int tid = threadIdx.x, w = tid >> 5, lane = tid & 31;
    const int bl = lane & 15, half = lane >> 4;
    const int b0 = blockIdx.x * 16;

    for (int i = tid; i < D_IN * 4; i += 512) {
        const int k = i >> 2, q = (i & 3) * 4;
        const float4 v = *(const float4*)(AT + (size_t)k * BATCH + b0 + q);
        float* d = sA + k * 17 + q;
        d[0] = v.x; d[1] = v.y; d[2] = v.z; d[3] = v.w;
    }
    __syncthreads();
    const char* lptr = (const char*)smem + bl * 4;

    const int r0 = blockIdx.y * rows_per_blk;
    int r1 = r0 + rows_per_blk; if (r1 > HID) r1 = HID;

#pragma unroll 1
    for (int n = r0 + w; n < r1; n += 16) {
        const int c4 = cnt[n] >> 1;
        const float4* p4 = (const float4*)(pairs + (size_t)n * SLOTS_F);
        float a0 = 0.f, a1 = 0.f;
        if (c4) {
            float4 A = p4[0], B = p4[1], C = p4[2], D = p4[3];
#pragma unroll 1
            for (int j = 4; j < c4; j += 4) {
                const float4 nA = p4[j],     nB = p4[j + 1];
                const float4 nC = p4[j + 2], nD = p4[j + 3];
                a0 = fmaf(GATHER(half ? A.w : A.y), half ? A.z : A.x, a0);
                a1 = fmaf(GATHER(half ? B.w : B.y), half ? B.z : B.x, a1);
                a0 = fmaf(GATHER(half ? C.w : C.y), half ? C.z : C.x, a0);
                a1 = fmaf(GATHER(half ? D.w : D.y), half ? D.z : D.x, a1);
                A = nA; B = nB; C = nC; D = nD;
            }
            a0 = fmaf(GATHER(half ? A.w : A.y), half ? A.z : A.x, a0);
            a1 = fmaf(GATHER(half ? B.w : B.y), half ? B.z : B.x, a1);
            a0 = fmaf(GATHER(half ? C.w : C.y), half ? C.z : C.x, a0);
            a1 = fmaf(GATHER(half ? D.w : D.y), half ? D.z : D.x, a1);
        }
        float acc = a0 + a1;
        acc += __shfl_xor_sync(0xffffffffu, acc, 16);
        if (half == 0) Yt[(size_t)n * BATCH + b0 + bl] = acc;
    }
}

/* ------------------------------------------------------------------
 * Exact top-K per batch row: keys/values in registers, per-bit
 * counters in smem, 1 sync per round.
 * ------------------------------------------------------------------ */
__global__ __launch_bounds__(256)
void topk_k(const float* __restrict__ V, float* __restrict__ H)
{
    const int b = blockIdx.x, tid = threadIdx.x;
    __shared__ int scnt[32];
    if (tid < 32) scnt[tid] = 0;

    float v[8]; unsigned key[8];
#pragma unroll
    for (int e = 0; e < 8; e++) {
        const float x = V[(size_t)b * HID + e * 256 + tid];
        v[e] = x;
        const unsigned ui = __float_as_uint(x);
        key[e] = (ui & 0x80000000u) ? ~ui : (ui | 0x80000000u);
    }
    __syncthreads();

    unsigned T = 0u;
    for (int bit = 31; bit >= 0; bit--) {
        const unsigned cand = T | (1u << bit);
        int c = 0;
#pragma unroll
        for (int e = 0; e < 8; e++) c += (key[e] >= cand) ? 1 : 0;
        for (int o = 16; o; o >>= 1) c += __shfl_down_sync(0xffffffffu, c, o);
        if ((tid & 31) == 0) atomicAdd(&scnt[bit], c);
        __syncthreads();
        if (scnt[bit] >= KWIN) T = cand;
    }

#pragma unroll
    for (int e = 0; e < 8; e++)
        H[(size_t)b * HID + e * 256 + tid] = (key[e] >= T) ? v[e] : 0.f;
}

/* ------------------------------------------------------------------ */
__global__ __launch_bounds__(128)
void head_k(const float* __restrict__ H,
            const float* __restrict__ Wex, const float* __restrict__ Wix,
            const float* __restrict__ Wei, const float* __restrict__ bo,
            float* __restrict__ out)
{
    const int b = blockIdx.x, tid = threadIdx.x;
    __shared__ __align__(16) float sh[HID];
    __shared__ float sred[4];

    for (int k = tid; k < HID; k += 128) sh[k] = H[(size_t)b * HID + k];
    __syncthreads();

    float p = 0.f;
    for (int k = tid; k < HID; k += 128) p += sh[k] * Wix[k];
    for (int o = 16; o; o >>= 1) p += __shfl_down_sync(0xffffffffu, p, o);
    if ((tid & 31) == 0) sred[tid >> 5] = p;
    __syncthreads();
    const float S = sred[0] + sred[1] + sred[2] + sred[3];

    if (tid < OUT_N) {
        const float* wrow = Wex + (size_t)tid * HID;
        float acc = 0.f;
#pragma unroll 4
        for (int k = 0; k < HID; k += 4) {
            const float4 wq = *(const float4*)(wrow + k);
            acc = fmaf(sh[k + 0], wq.x, acc);
            acc = fmaf(sh[k + 1], wq.y, acc);
            acc = fmaf(sh[k + 2], wq.z, acc);
            acc = fmaf(sh[k + 3], wq.w, acc);
        }
        out[(size_t)b * OUT_N + tid] = acc - Wei[tid] * S + bo[tid];
    }
}

/* ------------------------------------------------------------------ */
extern "C" void kernel_launch(void* const* d_in, const int* in_sizes, int n_in,
                              void* d_out, int out_size)
{
    (void)in_sizes; (void)n_in; (void)out_size;
    const float* x      = (const float*)d_in[0];
    const float* ctx    = (const float*)d_in[1];
    const float* W1     = (const float*)d_in[2];
    const float* b1     = (const float*)d_in[3];
    const float* segW1  = (const float*)d_in[4];
    const float* maskW1 = (const float*)d_in[5];
    const float* maskS1 = (const float*)d_in[6];
    const float* W2     = (const float*)d_in[7];
    const float* b2     = (const float*)d_in[8];
    const float* segW2  = (const float*)d_in[9];
    const float* maskW2 = (const float*)d_in[10];
    const float* maskS2 = (const float*)d_in[11];
    const float* Wex    = (const float*)d_in[12];
    const float* Wix    = (const float*)d_in[13];
    const float* Wei    = (const float*)d_in[14];
    const float* bo     = (const float*)d_in[15];
    float* out = (float*)d_out;

    float *pCT, *pXT, *pYt, *pV, *pH, *pHT;
    cudaGetSymbolAddress((void**)&pCT, g_CT);
    cudaGetSymbolAddress((void**)&pXT, g_XT);
    cudaGetSymbolAddress((void**)&pYt, g_Yt);
    cudaGetSymbolAddress((void**)&pV,  g_V);
    cudaGetSymbolAddress((void**)&pH,  g_H);
    cudaGetSymbolAddress((void**)&pHT, g_HT);

    float2 *dp1, *dp2, *fp1, *fp2;
    int *dc1, *dc2, *fc1, *fc2;
    cudaGetSymbolAddress((void**)&dp1, g_dp1); cudaGetSymbolAddress((void**)&dc1, g_dc1);
    cudaGetSymbolAddress((void**)&dp2, g_dp2); cudaGetSymbolAddress((void**)&dc2, g_dc2);
    cudaGetSymbolAddress((void**)&fp1, g_fp1); cudaGetSymbolAddress((void**)&fc1, g_fc1);
    cudaGetSymbolAddress((void**)&fp2, g_fp2); cudaGetSymbolAddress((void**)&fc2, g_fc2);

    const int smemF = D_IN * 17 * 4;                     /* 139264 */
    const int smemD = D_CTX * 32 * 4 + 128 * 33 * 4;     /* 147968 */
    cudaFuncSetAttribute((const void*)ff_mm,
                         cudaFuncAttributeMaxDynamicSharedMemorySize, smemF);
    cudaFuncSetAttribute((const void*)dend_gate,
                         cudaFuncAttributeMaxDynamicSharedMemorySize, smemD);

    /* activation transposes */
    transpose_k<<<dim3(D_CTX / 32, BATCH / 32), dim3(32, 8)>>>(ctx, pCT, BATCH, D_CTX);
    transpose_k<<<dim3(D_IN  / 32, BATCH / 32), dim3(32, 8)>>>(x,   pXT, BATCH, D_IN);

    /* weight compaction. offset premult: dend smem stride 32 floats ->
       idx*128 bytes; FF stride 17 floats -> idx*68 bytes */
    compact_k<SLOTS_D><<<NDEND / 32, 256>>>(segW1, maskS1, dp1, dc1, NDEND, D_CTX, 128);
    compact_k<SLOTS_D><<<NDEND / 32, 256>>>(segW2, maskS2, dp2, dc2, NDEND, D_CTX, 128);
    compact_k<SLOTS_F><<<HID / 32,   256>>>(W1,    maskW1, fp1, fc1, HID, D_IN, 68);
    compact_k<SLOTS_F><<<HID / 32,   256>>>(W2,    maskW2, fp2, fc2, HID, HID,  68);

    const int rpbF = (HID + 8) / 9;   /* 228, grid 16x9 = 144 blocks */

    /* layer 1 */
    ff_mm<<<dim3(16, 9), 512, smemF>>>(pXT, fp1, fc1, pYt, rpbF);
    dend_gate<<<dim3(8, 16), 512, smemD>>>(pCT, dp1, dc1, pYt, b1, pV);
    topk_k<<<BATCH, 256>>>(pV, pH);
    transpose_k<<<dim3(HID / 32, BATCH / 32), dim3(32, 8)>>>(pH, pHT, BATCH, HID);

    /* layer 2 */
    ff_mm<<<dim3(16, 9), 512, smemF>>>(pHT, fp2, fc2, pYt, rpbF);
    dend_gate<<<dim3(8, 16), 512, smemD>>>(pCT, dp2, dc2, pYt, b2, pV);
    topk_k<<<BATCH, 256>>>(pV, pH);

    /* Dale output head */
    head_k<<<BATCH, 128>>>(pH, Wex, Wix, Wei, bo, out);
}

// round 8
// speedup vs baseline: 3.7058x; 1.8458x over previous
#include <cuda_runtime.h>
#include <math.h>

#define BATCH 256
#define D_IN  2048
#define HID   2048
#define NSEG  10
#define D_CTX 1024
#define OUT_N 100
#define KWIN  102
#define NDEND (HID * NSEG)   /* 20480 */

#define SLOTS_D 112   /* dendrite rows: Binom(1024,.05) mean 51.2 sd 7.0, mult of 8 */
#define SLOTS_F 176   /* FF rows: Binom(2048,.05) mean 102.4 sd 9.9, mult of 8 */

/* ---------------- scratch (no allocations allowed) ----------------
 * pair arrays oversized by one row / 32 rows so cross-row prefetch
 * can read past the last row harmlessly. */
__device__ float  g_CT [(size_t)D_CTX * BATCH];
__device__ float  g_XT [(size_t)D_IN  * BATCH];
__device__ float  g_Yt [(size_t)HID   * BATCH];
__device__ float  g_V  [(size_t)BATCH * HID];
__device__ float  g_H  [(size_t)BATCH * HID];
__device__ float  g_HT [(size_t)HID   * BATCH];

__device__ float2 g_dp1[(size_t)(NDEND + 1) * SLOTS_D];
__device__ int    g_dc1[NDEND];
__device__ float2 g_dp2[(size_t)(NDEND + 1) * SLOTS_D];
__device__ int    g_dc2[NDEND];
__device__ float2 g_fp1[(size_t)(HID + 32) * SLOTS_F];
__device__ int    g_fc1[HID + 32];
__device__ float2 g_fp2[(size_t)(HID + 32) * SLOTS_F];
__device__ int    g_fc2[HID + 32];

/* ------------------------------------------------------------------ */
__global__ __launch_bounds__(256)
void transpose_k(const float* __restrict__ in, float* __restrict__ out,
                 int rows, int cols)
{
    __shared__ float t[32][33];
    const int cb = blockIdx.x * 32, rb = blockIdx.y * 32;
    const int tx = threadIdx.x, ty = threadIdx.y;  /* 32 x 8 */
#pragma unroll
    for (int i = 0; i < 32; i += 8)
        t[ty + i][tx] = in[(size_t)(rb + ty + i) * cols + cb + tx];
    __syncthreads();
#pragma unroll
    for (int i = 0; i < 32; i += 8)
        out[(size_t)(cb + ty + i) * rows + rb + tx] = t[tx][ty + i];
}

/* ------------------------------------------------------------------
 * Deterministic two-sweep compaction, one warp per row, both layers
 * in one launch. Sweep 1: all chunk ballots (independent loads, full
 * MLP). Warp prefix-scan -> per-chunk exclusive base. Sweep 2: fully
 * independent predicated weight loads + pair stores. Pads count to a
 * multiple of 8 with zero pairs (offset 0 -> harmless FMA of 0).
 * ------------------------------------------------------------------ */
template<int CHUNKS, int SLOTS>
__global__ __launch_bounds__(256)
void compact2(const float* __restrict__ Wa, const float* __restrict__ Ma,
              float2* __restrict__ Pa, int* __restrict__ Ca,
              const float* __restrict__ Wb, const float* __restrict__ Mb,
              float2* __restrict__ Pb, int* __restrict__ Cb,
              int rows, int mult)
{
    const int K = CHUNKS * 32;
    int row = blockIdx.x * 8 + (threadIdx.x >> 5);
    const float *W, *M; float2* P; int* C;
    if (row < rows) { W = Wa; M = Ma; P = Pa; C = Ca; }
    else            { W = Wb; M = Mb; P = Pb; C = Cb; row -= rows; }
    const int lane = threadIdx.x & 31;
    const unsigned lm = (1u << lane) - 1u;
    const float* mrow = M + (size_t)row * K;
    const float* wrow = W + (size_t)row * K;
    float2* prow = P + (size_t)row * SLOTS;

    unsigned my0 = 0, my1 = 0;
#pragma unroll
    for (int c = 0; c < 32; c++) {
        const unsigned bal = __ballot_sync(0xffffffffu, mrow[c * 32 + lane] != 0.f);
        if (lane == c) my0 = bal;
    }
    if (CHUNKS == 64) {
#pragma unroll
        for (int c = 0; c < 32; c++) {
            const unsigned bal = __ballot_sync(0xffffffffu, mrow[(c + 32) * 32 + lane] != 0.f);
            if (lane == c) my1 = bal;
        }
    }

    const int v0 = __popc(my0);
    int incl = v0;
#pragma unroll
    for (int o = 1; o < 32; o <<= 1) {
        const int tt = __shfl_up_sync(0xffffffffu, incl, o);
        if (lane >= o) incl += tt;
    }
    const int base0 = incl - v0;
    int total = __shfl_sync(0xffffffffu, incl, 31);
    int base1 = 0;
    if (CHUNKS == 64) {
        const int v1 = __popc(my1);
        int incl1 = v1;
#pragma unroll
        for (int o = 1; o < 32; o <<= 1) {
            const int tt = __shfl_up_sync(0xffffffffu, incl1, o);
            if (lane >= o) incl1 += tt;
        }
        base1 = total + incl1 - v1;
        total += __shfl_sync(0xffffffffu, incl1, 31);
    }

#pragma unroll 4
    for (int c = 0; c < CHUNKS; c++) {
        unsigned bal; int cb;
        if (c < 32) { bal = __shfl_sync(0xffffffffu, my0, c);
                      cb  = __shfl_sync(0xffffffffu, base0, c); }
        else        { bal = __shfl_sync(0xffffffffu, my1, c - 32);
                      cb  = __shfl_sync(0xffffffffu, base1, c - 32); }
        if ((bal >> lane) & 1u) {
            const int p = cb + __popc(bal & lm);
            if (p < SLOTS)
                prow[p] = make_float2(wrow[c * 32 + lane],
                                      __int_as_float((c * 32 + lane) * mult));
        }
    }

    int b = total > SLOTS ? SLOTS : total;
    int padded = (b + 7) & ~7; if (padded > SLOTS) padded = SLOTS;
    if (lane < padded - b) prow[b + lane] = make_float2(0.f, __int_as_float(0));
    if (lane == 0) C[row] = padded;
}

#define GATHER(off) (*(const float*)(lptr + __float_as_int(off)))

/* ------------------------------------------------------------------
 * Fused dendrite GEMM + abs-argmax + sigmoid gate. BSUB=32,
 * 1024 threads (32 warps/SM). sA = CT chunk [1024][32] -> stride-32
 * conflict-free gather. Per warp: 4 units x 10 segments = 40
 * consecutive pair rows, software-pipelined ACROSS rows: counts
 * loaded once via 1-2 LDGs + shfl; next row's head (4 float4)
 * prefetched during current row's tail. No dependent-chain prologue.
 * ------------------------------------------------------------------ */
__global__ __launch_bounds__(1024)
void dend_gate(const float* __restrict__ CT, const float2* __restrict__ pairs,
               const int* __restrict__ cnt, const float* __restrict__ Yt,
               const float* __restrict__ bias, float* __restrict__ V)
{
    extern __shared__ __align__(16) char smem[];
    float* sA   = (float*)smem;                              /* [1024][32] */
    float* tile = (float*)(smem + (size_t)D_CTX * 32 * 4);   /* [128][33]  */
    const int tid = threadIdx.x, w = tid >> 5, lane = tid & 31;
    const int b0 = blockIdx.x * 32, u0 = blockIdx.y * 128;

    for (int i = tid; i < D_CTX * 8; i += 1024) {
        const int k = i >> 3, q = (i & 7) * 4;
        *(float4*)(sA + k * 32 + q) =
            *(const float4*)(CT + (size_t)k * BATCH + b0 + q);
    }
    __syncthreads();
    const char* lptr = (const char*)smem + lane * 4;

    const int ubase = u0 + w * 4;            /* 4 units per warp   */
    const int rbase = ubase * NSEG;          /* 40 consecutive rows */
    const int c0r = cnt[rbase + lane];
    const int c1r = (lane < 8) ? cnt[rbase + 32 + lane] : 0;

    const float4* p4 = (const float4*)(pairs + (size_t)rbase * SLOTS_D);
    float4 A = p4[0], B = p4[1], C = p4[2], D = p4[3];

    int t = 0;
#pragma unroll 1
    for (int i = 0; i < 4; i++) {
        float best = 0.f, besta = -1.f;
#pragma unroll 1
        for (int s = 0; s < NSEG; s++, t++) {
            const int cthis = (t < 32) ? __shfl_sync(0xffffffffu, c0r, t)
                                       : __shfl_sync(0xffffffffu, c1r, t - 32);
            const int c4 = cthis >> 1;
            const float4* pn = p4 + (SLOTS_D / 2);
            float a0 = 0.f, a1 = 0.f, a2 = 0.f, a3 = 0.f;
#pragma unroll 1
            for (int j = 4; j < c4; j += 4) {
                const float4 nA = p4[j],     nB = p4[j + 1];
                const float4 nC = p4[j + 2], nD = p4[j + 3];
                a0 = fmaf(GATHER(A.y), A.x, a0);
                a0 = fmaf(GATHER(A.w), A.z, a0);
                a1 = fmaf(GATHER(B.y), B.x, a1);
                a1 = fmaf(GATHER(B.w), B.z, a1);
                a2 = fmaf(GATHER(C.y), C.x, a2);
                a2 = fmaf(GATHER(C.w), C.z, a2);
                a3 = fmaf(GATHER(D.y), D.x, a3);
                a3 = fmaf(GATHER(D.w), D.z, a3);
                A = nA; B = nB; C = nC; D = nD;
            }
            /* prefetch next row's head while finishing this row */
            const float4 hA = pn[0], hB = pn[1], hC = pn[2], hD = pn[3];
            a0 = fmaf(GATHER(A.y), A.x, a0);
            a0 = fmaf(GATHER(A.w), A.z, a0);
            a1 = fmaf(GATHER(B.y), B.x, a1);
            a1 = fmaf(GATHER(B.w), B.z, a1);
            a2 = fmaf(GATHER(C.y), C.x, a2);
            a2 = fmaf(GATHER(C.w), C.z, a2);
            a3 = fmaf(GATHER(D.y), D.x, a3);
            a3 = fmaf(GATHER(D.w), D.z, a3);
            A = hA; B = hB; C = hC; D = hD; p4 = pn;

            const float acc = (a0 + a1) + (a2 + a3);
            const float aa = fabsf(acc);
            if (aa > besta) { besta = aa; best = acc; }   /* first max */
        }
        const int u = ubase + i;
        const float y = Yt[(size_t)u * BATCH + b0 + lane] + bias[u];
        tile[(w * 4 + i) * 33 + lane] = y * (1.f / (1.f + expf(-best)));
    }
    __syncthreads();

    for (int i = tid; i < 128 * 32; i += 1024) {
        const int uu = i & 127, bb = i >> 7;
        V[(size_t)(b0 + bb) * HID + u0 + uu] = tile[uu * 33 + bb];
    }
}

/* ------------------------------------------------------------------
 * FF sparse GEMM, BSUB=16 half-split, 1024 threads, cross-row
 * pipelining (next row's cnt + head prefetched during current row).
 * sA = AT chunk [2048][17].
 * ------------------------------------------------------------------ */
__global__ __launch_bounds__(1024)
void ff_mm(const float* __restrict__ AT, const float2* __restrict__ pairs,
           const int* __restrict__ cnt, float* __restrict__ Yt,
           int rows_per_blk)
{
    extern __shared__ __align__(16) char smem[];
    float* sA = (float*)smem;                       /* [2048][17] */
    const int tid = threadIdx.x, w = tid >> 5, lane = tid & 31;
    const int bl = lane & 15, half = lane >> 4;
    const int b0 = blockIdx.x * 16;

    for (int i = tid; i < D_IN * 4; i += 1024) {
        const int k = i >> 2, q = (i & 3) * 4;
        const float4 v = *(const float4*)(AT + (size_t)k * BATCH + b0 + q);
        float* d = sA + k * 17 + q;
        d[0] = v.x; d[1] = v.y; d[2] = v.z; d[3] = v.w;
    }
    __syncthreads();
    const char* lptr = (const char*)smem + bl * 4;

    const int r0 = blockIdx.y * rows_per_blk;
    int r1 = r0 + rows_per_blk; if (r1 > HID) r1 = HID;

    int n = r0 + w;
    if (n < r1) {
        const float4* p4 = (const float4*)(pairs + (size_t)n * SLOTS_F);
        float4 A = p4[0], B = p4[1], C = p4[2], D = p4[3];
        int c = cnt[n];
#pragma unroll 1
        while (n < r1) {
            const int nn = n + 32;
            const int c4 = c >> 1;
            const int cnext = cnt[nn];          /* oversized array */
            const float4* pn = p4 + 32 * (SLOTS_F / 2);
            float a0 = 0.f, a1 = 0.f;
#pragma unroll 1
            for (int j = 4; j < c4; j += 4) {
                const float4 nA = p4[j],     nB = p4[j + 1];
                const float4 nC = p4[j + 2], nD = p4[j + 3];
                a0 = fmaf(GATHER(half ? A.w : A.y), half ? A.z : A.x, a0);
                a1 = fmaf(GATHER(half ? B.w : B.y), half ? B.z : B.x, a1);
                a0 = fmaf(GATHER(half ? C.w : C.y), half ? C.z : C.x, a0);
                a1 = fmaf(GATHER(half ? D.w : D.y), half ? D.z : D.x, a1);
                A = nA; B = nB; C = nC; D = nD;
            }
            const float4 hA = pn[0], hB = pn[1], hC = pn[2], hD = pn[3];
            a0 = fmaf(GATHER(half ? A.w : A.y), half ? A.z : A.x, a0);
            a1 = fmaf(GATHER(half ? B.w : B.y), half ? B.z : B.x, a1);
            a0 = fmaf(GATHER(half ? C.w : C.y), half ? C.z : C.x, a0);
            a1 = fmaf(GATHER(half ? D.w : D.y), half ? D.z : D.x, a1);

            float acc = a0 + a1;
            acc += __shfl_xor_sync(0xffffffffu, acc, 16);
            if (half == 0) Yt[(size_t)n * BATCH + b0 + bl] = acc;

            A = hA; B = hB; C = hC; D = hD; p4 = pn; c = cnext; n = nn;
        }
    }
}

/* ------------------------------------------------------------------
 * Exact top-K per batch row: keys/values in registers, per-bit
 * counters in smem, 1 sync per round.
 * ------------------------------------------------------------------ */
__global__ __launch_bounds__(256)
void topk_k(const float* __restrict__ V, float* __restrict__ H)
{
    const int b = blockIdx.x, tid = threadIdx.x;
    __shared__ int scnt[32];
    if (tid < 32) scnt[tid] = 0;

    float v[8]; unsigned key[8];
#pragma unroll
    for (int e = 0; e < 8; e++) {
        const float x = V[(size_t)b * HID + e * 256 + tid];
        v[e] = x;
        const unsigned ui = __float_as_uint(x);
        key[e] = (ui & 0x80000000u) ? ~ui : (ui | 0x80000000u);
    }
    __syncthreads();

    unsigned T = 0u;
    for (int bit = 31; bit >= 0; bit--) {
        const unsigned cand = T | (1u << bit);
        int c = 0;
#pragma unroll
        for (int e = 0; e < 8; e++) c += (key[e] >= cand) ? 1 : 0;
        for (int o = 16; o; o >>= 1) c += __shfl_down_sync(0xffffffffu, c, o);
        if ((tid & 31) == 0) atomicAdd(&scnt[bit], c);
        __syncthreads();
        if (scnt[bit] >= KWIN) T = cand;
    }

#pragma unroll
    for (int e = 0; e < 8; e++)
        H[(size_t)b * HID + e * 256 + tid] = (key[e] >= T) ? v[e] : 0.f;
}

/* ------------------------------------------------------------------ */
__global__ __launch_bounds__(128)
void head_k(const float* __restrict__ H,
            const float* __restrict__ Wex, const float* __restrict__ Wix,
            const float* __restrict__ Wei, const float* __restrict__ bo,
            float* __restrict__ out)
{
    const int b = blockIdx.x, tid = threadIdx.x;
    __shared__ __align__(16) float sh[HID];
    __shared__ float sred[4];

    for (int k = tid; k < HID; k += 128) sh[k] = H[(size_t)b * HID + k];
    __syncthreads();

    float p = 0.f;
    for (int k = tid; k < HID; k += 128) p += sh[k] * Wix[k];
    for (int o = 16; o; o >>= 1) p += __shfl_down_sync(0xffffffffu, p, o);
    if ((tid & 31) == 0) sred[tid >> 5] = p;
    __syncthreads();
    const float S = sred[0] + sred[1] + sred[2] + sred[3];

    if (tid < OUT_N) {
        const float* wrow = Wex + (size_t)tid * HID;
        float acc = 0.f;
#pragma unroll 4
        for (int k = 0; k < HID; k += 4) {
            const float4 wq = *(const float4*)(wrow + k);
            acc = fmaf(sh[k + 0], wq.x, acc);
            acc = fmaf(sh[k + 1], wq.y, acc);
            acc = fmaf(sh[k + 2], wq.z, acc);
            acc = fmaf(sh[k + 3], wq.w, acc);
        }
        out[(size_t)b * OUT_N + tid] = acc - Wei[tid] * S + bo[tid];
    }
}

/* ------------------------------------------------------------------ */
extern "C" void kernel_launch(void* const* d_in, const int* in_sizes, int n_in,
                              void* d_out, int out_size)
{
    (void)in_sizes; (void)n_in; (void)out_size;
    const float* x      = (const float*)d_in[0];
    const float* ctx    = (const float*)d_in[1];
    const float* W1     = (const float*)d_in[2];
    const float* b1     = (const float*)d_in[3];
    const float* segW1  = (const float*)d_in[4];
    const float* maskW1 = (const float*)d_in[5];
    const float* maskS1 = (const float*)d_in[6];
    const float* W2     = (const float*)d_in[7];
    const float* b2     = (const float*)d_in[8];
    const float* segW2  = (const float*)d_in[9];
    const float* maskW2 = (const float*)d_in[10];
    const float* maskS2 = (const float*)d_in[11];
    const float* Wex    = (const float*)d_in[12];
    const float* Wix    = (const float*)d_in[13];
    const float* Wei    = (const float*)d_in[14];
    const float* bo     = (const float*)d_in[15];
    float* out = (float*)d_out;

    float *pCT, *pXT, *pYt, *pV, *pH, *pHT;
    cudaGetSymbolAddress((void**)&pCT, g_CT);
    cudaGetSymbolAddress((void**)&pXT, g_XT);
    cudaGetSymbolAddress((void**)&pYt, g_Yt);
    cudaGetSymbolAddress((void**)&pV,  g_V);
    cudaGetSymbolAddress((void**)&pH,  g_H);
    cudaGetSymbolAddress((void**)&pHT, g_HT);

    float2 *dp1, *dp2, *fp1, *fp2;
    int *dc1, *dc2, *fc1, *fc2;
    cudaGetSymbolAddress((void**)&dp1, g_dp1); cudaGetSymbolAddress((void**)&dc1, g_dc1);
    cudaGetSymbolAddress((void**)&dp2, g_dp2); cudaGetSymbolAddress((void**)&dc2, g_dc2);
    cudaGetSymbolAddress((void**)&fp1, g_fp1); cudaGetSymbolAddress((void**)&fc1, g_fc1);
    cudaGetSymbolAddress((void**)&fp2, g_fp2); cudaGetSymbolAddress((void**)&fc2, g_fc2);

    const int smemF = D_IN * 17 * 4;                     /* 139264 */
    const int smemD = D_CTX * 32 * 4 + 128 * 33 * 4;     /* 147968 */
    cudaFuncSetAttribute((const void*)ff_mm,
                         cudaFuncAttributeMaxDynamicSharedMemorySize, smemF);
    cudaFuncSetAttribute((const void*)dend_gate,
                         cudaFuncAttributeMaxDynamicSharedMemorySize, smemD);

    /* activation transposes */
    transpose_k<<<dim3(D_CTX / 32, BATCH / 32), dim3(32, 8)>>>(ctx, pCT, BATCH, D_CTX);
    transpose_k<<<dim3(D_IN  / 32, BATCH / 32), dim3(32, 8)>>>(x,   pXT, BATCH, D_IN);

    /* compaction: both dendrite layers in one launch, both FF layers
       in one launch. offset premult: dend smem stride 32 floats ->
       idx*128 bytes; FF stride 17 floats -> idx*68 bytes */
    compact2<32, SLOTS_D><<<2 * NDEND / 8, 256>>>(
        segW1, maskS1, dp1, dc1, segW2, maskS2, dp2, dc2, NDEND, 128);
    compact2<64, SLOTS_F><<<2 * HID / 8, 256>>>(
        W1, maskW1, fp1, fc1, W2, maskW2, fp2, fc2, HID, 68);

    const int rpbF = (HID + 8) / 9;   /* 228, grid 16x9 = 144 blocks */

    /* layer 1 */
    ff_mm<<<dim3(16, 9), 1024, smemF>>>(pXT, fp1, fc1, pYt, rpbF);
    dend_gate<<<dim3(8, 16), 1024, smemD>>>(pCT, dp1, dc1, pYt, b1, pV);
    topk_k<<<BATCH, 256>>>(pV, pH);
    transpose_k<<<dim3(HID / 32, BATCH / 32), dim3(32, 8)>>>(pH, pHT, BATCH, HID);

    /* layer 2 */
    ff_mm<<<dim3(16, 9), 1024, smemF>>>(pHT, fp2, fc2, pYt, rpbF);
    dend_gate<<<dim3(8, 16), 1024, smemD>>>(pCT, dp2, dc2, pYt, b2, pV);
    topk_k<<<BATCH, 256>>>(pV, pH);

    /* Dale output head */
    head_k<<<BATCH, 128>>>(pH, Wex, Wix, Wei, bo, out);
}

// round 9
// speedup vs baseline: 4.0237x; 1.0858x over previous
#include <cuda_runtime.h>
#include <math.h>

#define BATCH 256
#define D_IN  2048
#define HID   2048
#define NSEG  10
#define D_CTX 1024
#define OUT_N 100
#define KWIN  102
#define NDEND (HID * NSEG)   /* 20480 */

#define SLOTS_D 112   /* dendrite rows: Binom(1024,.05) mean 51.2 sd 7.0, mult of 8 */
#define SLOTS_F 176   /* FF rows: Binom(2048,.05) mean 102.4 sd 9.9, mult of 8 */

/* ---------------- scratch (no allocations allowed) ----------------
 * pair arrays oversized so cross-row prefetch can read past the last
 * row harmlessly. */
__device__ float  g_CT [(size_t)D_CTX * BATCH];
__device__ float  g_XT [(size_t)D_IN  * BATCH];
__device__ float  g_Yt [(size_t)HID   * BATCH];
__device__ float  g_V  [(size_t)BATCH * HID];
__device__ float  g_H  [(size_t)BATCH * HID];
__device__ float  g_HT [(size_t)HID   * BATCH];

__device__ float2 g_dp1[(size_t)(NDEND + 1) * SLOTS_D];
__device__ int    g_dc1[NDEND];
__device__ float2 g_dp2[(size_t)(NDEND + 1) * SLOTS_D];
__device__ int    g_dc2[NDEND];
__device__ float2 g_fp1[(size_t)(HID + 32) * SLOTS_F];
__device__ int    g_fc1[HID + 32];
__device__ float2 g_fp2[(size_t)(HID + 32) * SLOTS_F];
__device__ int    g_fc2[HID + 32];

/* ------------------------------------------------------------------ */
__global__ __launch_bounds__(256)
void transpose_k(const float* __restrict__ in, float* __restrict__ out,
                 int rows, int cols)
{
    __shared__ float t[32][33];
    const int cb = blockIdx.x * 32, rb = blockIdx.y * 32;
    const int tx = threadIdx.x, ty = threadIdx.y;  /* 32 x 8 */
#pragma unroll
    for (int i = 0; i < 32; i += 8)
        t[ty + i][tx] = in[(size_t)(rb + ty + i) * cols + cb + tx];
    __syncthreads();
#pragma unroll
    for (int i = 0; i < 32; i += 8)
        out[(size_t)(cb + ty + i) * rows + rb + tx] = t[tx][ty + i];
}

/* ------------------------------------------------------------------
 * Vectorized deterministic compaction, one warp per row, both layers
 * in one launch. Masks read as float4 (group of 4 chunks of 128
 * elements, double-buffered). Per-chunk counts packed into bytes of
 * one u32 -> single SIMD warp scan per group. Weights loaded as
 * float4 only when the lane's nibble is nonzero. Pair order =
 * (chunk, lane, q) -- deterministic; consumer sums order-agnostic.
 * Count padded to a multiple of 8 with zero pairs (offset 0 ->
 * harmless FMA of 0).
 * ------------------------------------------------------------------ */
template<int G, int SLOTS>   /* G = K/512 groups; K = G*512 */
__global__ __launch_bounds__(256)
void compact2v(const float* __restrict__ Wa, const float* __restrict__ Ma,
               float2* __restrict__ Pa, int* __restrict__ Ca,
               const float* __restrict__ Wb, const float* __restrict__ Mb,
               float2* __restrict__ Pb, int* __restrict__ Cb,
               int rows, int mult)
{
    const int K = G * 512;
    int row = blockIdx.x * 8 + (threadIdx.x >> 5);
    const float *W, *M; float2* P; int* C;
    if (row < rows) { W = Wa; M = Ma; P = Pa; C = Ca; }
    else            { W = Wb; M = Mb; P = Pb; C = Cb; row -= rows; }
    const int lane = threadIdx.x & 31;

    const float4* mrow4 = (const float4*)(M + (size_t)row * K);
    const float4* wrow4 = (const float4*)(W + (size_t)row * K);
    float2* prow = P + (size_t)row * SLOTS;

    float4 mb[4], nb[4];
#pragma unroll
    for (int c = 0; c < 4; c++) mb[c] = mrow4[c * 32 + lane];

    int base = 0;
#pragma unroll
    for (int g = 0; g < G; g++) {
        if (g + 1 < G) {
#pragma unroll
            for (int c = 0; c < 4; c++)
                nb[c] = mrow4[((g + 1) * 4 + c) * 32 + lane];
        }
        int nib[4];
        unsigned wrd = 0;
#pragma unroll
        for (int c = 0; c < 4; c++) {
            nib[c] = (mb[c].x != 0.f ? 1 : 0) | (mb[c].y != 0.f ? 2 : 0)
                   | (mb[c].z != 0.f ? 4 : 0) | (mb[c].w != 0.f ? 8 : 0);
            wrd |= (unsigned)__popc(nib[c]) << (8 * c);
        }
        /* SIMD byte-parallel inclusive scan over lanes */
        unsigned inc = wrd;
#pragma unroll
        for (int o = 1; o < 32; o <<= 1) {
            const unsigned t = __shfl_up_sync(0xffffffffu, inc, o);
            if (lane >= o) inc += t;
        }
        const unsigned tot = __shfl_sync(0xffffffffu, inc, 31);
        const unsigned exc = inc - wrd;

        int cbase[4];
        cbase[0] = base;
        cbase[1] = cbase[0] + (int)(tot & 255u);
        cbase[2] = cbase[1] + (int)((tot >> 8) & 255u);
        cbase[3] = cbase[2] + (int)((tot >> 16) & 255u);
        const int gtot = cbase[3] + (int)((tot >> 24) & 255u) - base;

#pragma unroll
        for (int c = 0; c < 4; c++) {
            if (nib[c]) {
                const float4 wq = wrow4[(g * 4 + c) * 32 + lane];
                int pos = cbase[c] + (int)((exc >> (8 * c)) & 255u);
                const int idx0 = (g * 4 + c) * 128 + lane * 4;
                if (nib[c] & 1) { if (pos < SLOTS)
                    prow[pos] = make_float2(wq.x, __int_as_float(idx0 * mult)); pos++; }
                if (nib[c] & 2) { if (pos < SLOTS)
                    prow[pos] = make_float2(wq.y, __int_as_float((idx0 + 1) * mult)); pos++; }
                if (nib[c] & 4) { if (pos < SLOTS)
                    prow[pos] = make_float2(wq.z, __int_as_float((idx0 + 2) * mult)); pos++; }
                if (nib[c] & 8) { if (pos < SLOTS)
                    prow[pos] = make_float2(wq.w, __int_as_float((idx0 + 3) * mult)); pos++; }
            }
        }
        base += gtot;
#pragma unroll
        for (int c = 0; c < 4; c++) mb[c] = nb[c];
    }

    int b = base > SLOTS ? SLOTS : base;
    int padded = (b + 7) & ~7; if (padded > SLOTS) padded = SLOTS;
    if (lane < padded - b) prow[b + lane] = make_float2(0.f, __int_as_float(0));
    if (lane == 0) C[row] = padded;
}

#define GATHER(off) (*(const float*)(lptr + __float_as_int(off)))

/* ------------------------------------------------------------------
 * Fused dendrite GEMM + abs-argmax + sigmoid gate. BSUB=32,
 * 1024 threads. sA = CT chunk [1024][32] -> stride-32 conflict-free
 * gather. Per warp: 4 units x 10 segments = 40 consecutive pair
 * rows, software-pipelined ACROSS rows (counts preloaded via shfl,
 * next row's head prefetched during current row's tail).
 * ------------------------------------------------------------------ */
__global__ __launch_bounds__(1024)
void dend_gate(const float* __restrict__ CT, const float2* __restrict__ pairs,
               const int* __restrict__ cnt, const float* __restrict__ Yt,
               const float* __restrict__ bias, float* __restrict__ V)
{
    extern __shared__ __align__(16) char smem[];
    float* sA   = (float*)smem;                              /* [1024][32] */
    float* tile = (float*)(smem + (size_t)D_CTX * 32 * 4);   /* [128][33]  */
    const int tid = threadIdx.x, w = tid >> 5, lane = tid & 31;
    const int b0 = blockIdx.x * 32, u0 = blockIdx.y * 128;

    for (int i = tid; i < D_CTX * 8; i += 1024) {
        const int k = i >> 3, q = (i & 7) * 4;
        *(float4*)(sA + k * 32 + q) =
            *(const float4*)(CT + (size_t)k * BATCH + b0 + q);
    }
    __syncthreads();
    const char* lptr = (const char*)smem + lane * 4;

    const int ubase = u0 + w * 4;
    const int rbase = ubase * NSEG;
    const int c0r = cnt[rbase + lane];
    const int c1r = (lane < 8) ? cnt[rbase + 32 + lane] : 0;

    const float4* p4 = (const float4*)(pairs + (size_t)rbase * SLOTS_D);
    float4 A = p4[0], B = p4[1], C = p4[2], D = p4[3];

    int t = 0;
#pragma unroll 1
    for (int i = 0; i < 4; i++) {
        float best = 0.f, besta = -1.f;
#pragma unroll 1
        for (int s = 0; s < NSEG; s++, t++) {
            const int cthis = (t < 32) ? __shfl_sync(0xffffffffu, c0r, t)
                                       : __shfl_sync(0xffffffffu, c1r, t - 32);
            const int c4 = cthis >> 1;
            const float4* pn = p4 + (SLOTS_D / 2);
            float a0 = 0.f, a1 = 0.f, a2 = 0.f, a3 = 0.f;
#pragma unroll 1
            for (int j = 4; j < c4; j += 4) {
                const float4 nA = p4[j],     nB = p4[j + 1];
                const float4 nC = p4[j + 2], nD = p4[j + 3];
                a0 = fmaf(GATHER(A.y), A.x, a0);
                a0 = fmaf(GATHER(A.w), A.z, a0);
                a1 = fmaf(GATHER(B.y), B.x, a1);
                a1 = fmaf(GATHER(B.w), B.z, a1);
                a2 = fmaf(GATHER(C.y), C.x, a2);
                a2 = fmaf(GATHER(C.w), C.z, a2);
                a3 = fmaf(GATHER(D.y), D.x, a3);
                a3 = fmaf(GATHER(D.w), D.z, a3);
                A = nA; B = nB; C = nC; D = nD;
            }
            const float4 hA = pn[0], hB = pn[1], hC = pn[2], hD = pn[3];
            a0 = fmaf(GATHER(A.y), A.x, a0);
            a0 = fmaf(GATHER(A.w), A.z, a0);
            a1 = fmaf(GATHER(B.y), B.x, a1);
            a1 = fmaf(GATHER(B.w), B.z, a1);
            a2 = fmaf(GATHER(C.y), C.x, a2);
            a2 = fmaf(GATHER(C.w), C.z, a2);
            a3 = fmaf(GATHER(D.y), D.x, a3);
            a3 = fmaf(GATHER(D.w), D.z, a3);
            A = hA; B = hB; C = hC; D = hD; p4 = pn;

            const float acc = (a0 + a1) + (a2 + a3);
            const float aa = fabsf(acc);
            if (aa > besta) { besta = aa; best = acc; }   /* first max */
        }
        const int u = ubase + i;
        const float y = Yt[(size_t)u * BATCH + b0 + lane] + bias[u];
        tile[(w * 4 + i) * 33 + lane] = y * (1.f / (1.f + expf(-best)));
    }
    __syncthreads();

    for (int i = tid; i < 128 * 32; i += 1024) {
        const int uu = i & 127, bb = i >> 7;
        V[(size_t)(b0 + bb) * HID + u0 + uu] = tile[uu * 33 + bb];
    }
}

/* ------------------------------------------------------------------
 * FF sparse GEMM, BSUB=16 half-split, 1024 threads, cross-row
 * pipelining. sA = AT chunk [2048][17].
 * ------------------------------------------------------------------ */
__global__ __launch_bounds__(1024)
void ff_mm(const float* __restrict__ AT, const float2* __restrict__ pairs,
           const int* __restrict__ cnt, float* __restrict__ Yt,
           int rows_per_blk)
{
    extern __shared__ __align__(16) char smem[];
    float* sA = (float*)smem;                       /* [2048][17] */
    const int tid = threadIdx.x, w = tid >> 5, lane = tid & 31;
    const int bl = lane & 15, half = lane >> 4;
    const int b0 = blockIdx.x * 16;

    for (int i = tid; i < D_IN * 4; i += 1024) {
        const int k = i >> 2, q = (i & 3) * 4;
        const float4 v = *(const float4*)(AT + (size_t)k * BATCH + b0 + q);
        float* d = sA + k * 17 + q;
        d[0] = v.x; d[1] = v.y; d[2] = v.z; d[3] = v.w;
    }
    __syncthreads();
    const char* lptr = (const char*)smem + bl * 4;

    const int r0 = blockIdx.y * rows_per_blk;
    int r1 = r0 + rows_per_blk; if (r1 > HID) r1 = HID;

    int n = r0 + w;
    if (n < r1) {
        const float4* p4 = (const float4*)(pairs + (size_t)n * SLOTS_F);
        float4 A = p4[0], B = p4[1], C = p4[2], D = p4[3];
        int c = cnt[n];
#pragma unroll 1
        while (n < r1) {
            const int nn = n + 32;
            const int c4 = c >> 1;
            const int cnext = cnt[nn];          /* oversized array */
            const float4* pn = p4 + 32 * (SLOTS_F / 2);
            float a0 = 0.f, a1 = 0.f;
#pragma unroll 1
            for (int j = 4; j < c4; j += 4) {
                const float4 nA = p4[j],     nB = p4[j + 1];
                const float4 nC = p4[j + 2], nD = p4[j + 3];
                a0 = fmaf(GATHER(half ? A.w : A.y), half ? A.z : A.x, a0);
                a1 = fmaf(GATHER(half ? B.w : B.y), half ? B.z : B.x, a1);
                a0 = fmaf(GATHER(half ? C.w : C.y), half ? C.z : C.x, a0);
                a1 = fmaf(GATHER(half ? D.w : D.y), half ? D.z : D.x, a1);
                A = nA; B = nB; C = nC; D = nD;
            }
            const float4 hA = pn[0], hB = pn[1], hC = pn[2], hD = pn[3];
            a0 = fmaf(GATHER(half ? A.w : A.y), half ? A.z : A.x, a0);
            a1 = fmaf(GATHER(half ? B.w : B.y), half ? B.z : B.x, a1);
            a0 = fmaf(GATHER(half ? C.w : C.y), half ? C.z : C.x, a0);
            a1 = fmaf(GATHER(half ? D.w : D.y), half ? D.z : D.x, a1);

            float acc = a0 + a1;
            acc += __shfl_xor_sync(0xffffffffu, acc, 16);
            if (half == 0) Yt[(size_t)n * BATCH + b0 + bl] = acc;

            A = hA; B = hB; C = hC; D = hD; p4 = pn; c = cnext; n = nn;
        }
    }
}

/* ------------------------------------------------------------------
 * Exact top-K per batch row: keys/values in registers, per-bit
 * counters in smem, 1 sync per round. Optionally also writes the
 * transposed output HT[u][b] (fuses the inter-layer transpose).
 * ------------------------------------------------------------------ */
__global__ __launch_bounds__(256)
void topk_k(const float* __restrict__ V, float* __restrict__ H,
            float* __restrict__ HT)
{
    const int b = blockIdx.x, tid = threadIdx.x;
    __shared__ int scnt[32];
    if (tid < 32) scnt[tid] = 0;

    float v[8]; unsigned key[8];
#pragma unroll
    for (int e = 0; e < 8; e++) {
        const float x = V[(size_t)b * HID + e * 256 + tid];
        v[e] = x;
        const unsigned ui = __float_as_uint(x);
        key[e] = (ui & 0x80000000u) ? ~ui : (ui | 0x80000000u);
    }
    __syncthreads();

    unsigned T = 0u;
    for (int bit = 31; bit >= 0; bit--) {
        const unsigned cand = T | (1u << bit);
        int c = 0;
#pragma unroll
        for (int e = 0; e < 8; e++) c += (key[e] >= cand) ? 1 : 0;
        for (int o = 16; o; o >>= 1) c += __shfl_down_sync(0xffffffffu, c, o);
        if ((tid & 31) == 0) atomicAdd(&scnt[bit], c);
        __syncthreads();
        if (scnt[bit] >= KWIN) T = cand;
    }

#pragma unroll
    for (int e = 0; e < 8; e++) {
        const float o = (key[e] >= T) ? v[e] : 0.f;
        H[(size_t)b * HID + e * 256 + tid] = o;
        if (HT) HT[(size_t)(e * 256 + tid) * BATCH + b] = o;
    }
}

/* ------------------------------------------------------------------ */
__global__ __launch_bounds__(128)
void head_k(const float* __restrict__ H,
            const float* __restrict__ Wex, const float* __restrict__ Wix,
            const float* __restrict__ Wei, const float* __restrict__ bo,
            float* __restrict__ out)
{
    const int b = blockIdx.x, tid = threadIdx.x;
    __shared__ __align__(16) float sh[HID];
    __shared__ float sred[4];

    for (int k = tid; k < HID; k += 128) sh[k] = H[(size_t)b * HID + k];
    __syncthreads();

    float p = 0.f;
    for (int k = tid; k < HID; k += 128) p += sh[k] * Wix[k];
    for (int o = 16; o; o >>= 1) p += __shfl_down_sync(0xffffffffu, p, o);
    if ((tid & 31) == 0) sred[tid >> 5] = p;
    __syncthreads();
    const float S = sred[0] + sred[1] + sred[2] + sred[3];

    if (tid < OUT_N) {
        const float* wrow = Wex + (size_t)tid * HID;
        float acc = 0.f;
#pragma unroll 4
        for (int k = 0; k < HID; k += 4) {
            const float4 wq = *(const float4*)(wrow + k);
            acc = fmaf(sh[k + 0], wq.x, acc);
            acc = fmaf(sh[k + 1], wq.y, acc);
            acc = fmaf(sh[k + 2], wq.z, acc);
            acc = fmaf(sh[k + 3], wq.w, acc);
        }
        out[(size_t)b * OUT_N + tid] = acc - Wei[tid] * S + bo[tid];
    }
}

/* ------------------------------------------------------------------ */
extern "C" void kernel_launch(void* const* d_in, const int* in_sizes, int n_in,
                              void* d_out, int out_size)
{
    (void)in_sizes; (void)n_in; (void)out_size;
    const float* x      = (const float*)d_in[0];
    const float* ctx    = (const float*)d_in[1];
    const float* W1     = (const float*)d_in[2];
    const float* b1     = (const float*)d_in[3];
    const float* segW1  = (const float*)d_in[4];
    const float* maskW1 = (const float*)d_in[5];
    const float* maskS1 = (const float*)d_in[6];
    const float* W2     = (const float*)d_in[7];
    const float* b2     = (const float*)d_in[8];
    const float* segW2  = (const float*)d_in[9];
    const float* maskW2 = (const float*)d_in[10];
    const float* maskS2 = (const float*)d_in[11];
    const float* Wex    = (const float*)d_in[12];
    const float* Wix    = (const float*)d_in[13];
    const float* Wei    = (const float*)d_in[14];
    const float* bo     = (const float*)d_in[15];
    float* out = (float*)d_out;

    float *pCT, *pXT, *pYt, *pV, *pH, *pHT;
    cudaGetSymbolAddress((void**)&pCT, g_CT);
    cudaGetSymbolAddress((void**)&pXT, g_XT);
    cudaGetSymbolAddress((void**)&pYt, g_Yt);
    cudaGetSymbolAddress((void**)&pV,  g_V);
    cudaGetSymbolAddress((void**)&pH,  g_H);
    cudaGetSymbolAddress((void**)&pHT, g_HT);

    float2 *dp1, *dp2, *fp1, *fp2;
    int *dc1, *dc2, *fc1, *fc2;
    cudaGetSymbolAddress((void**)&dp1, g_dp1); cudaGetSymbolAddress((void**)&dc1, g_dc1);
    cudaGetSymbolAddress((void**)&dp2, g_dp2); cudaGetSymbolAddress((void**)&dc2, g_dc2);
    cudaGetSymbolAddress((void**)&fp1, g_fp1); cudaGetSymbolAddress((void**)&fc1, g_fc1);
    cudaGetSymbolAddress((void**)&fp2, g_fp2); cudaGetSymbolAddress((void**)&fc2, g_fc2);

    const int smemF = D_IN * 17 * 4;                     /* 139264 */
    const int smemD = D_CTX * 32 * 4 + 128 * 33 * 4;     /* 147968 */
    cudaFuncSetAttribute((const void*)ff_mm,
                         cudaFuncAttributeMaxDynamicSharedMemorySize, smemF);
    cudaFuncSetAttribute((const void*)dend_gate,
                         cudaFuncAttributeMaxDynamicSharedMemorySize, smemD);

    /* activation transposes */
    transpose_k<<<dim3(D_CTX / 32, BATCH / 32), dim3(32, 8)>>>(ctx, pCT, BATCH, D_CTX);
    transpose_k<<<dim3(D_IN  / 32, BATCH / 32), dim3(32, 8)>>>(x,   pXT, BATCH, D_IN);

    /* vectorized compaction: both layers per launch. offset premult:
       dend smem stride 32 floats -> idx*128 bytes; FF stride 17 ->
       idx*68 bytes */
    compact2v<2, SLOTS_D><<<2 * NDEND / 8, 256>>>(
        segW1, maskS1, dp1, dc1, segW2, maskS2, dp2, dc2, NDEND, 128);
    compact2v<4, SLOTS_F><<<2 * HID / 8, 256>>>(
        W1, maskW1, fp1, fc1, W2, maskW2, fp2, fc2, HID, 68);

    const int rpbF = (HID + 8) / 9;   /* 228, grid 16x9 = 144 blocks */

    /* layer 1 */
    ff_mm<<<dim3(16, 9), 1024, smemF>>>(pXT, fp1, fc1, pYt, rpbF);
    dend_gate<<<dim3(8, 16), 1024, smemD>>>(pCT, dp1, dc1, pYt, b1, pV);
    topk_k<<<BATCH, 256>>>(pV, pH, pHT);    /* writes H and H^T */

    /* layer 2 */
    ff_mm<<<dim3(16, 9), 1024, smemF>>>(pHT, fp2, fc2, pYt, rpbF);
    dend_gate<<<dim3(8, 16), 1024, smemD>>>(pCT, dp2, dc2, pYt, b2, pV);
    topk_k<<<BATCH, 256>>>(pV, pH, (float*)0);

    /* Dale output head */
    head_k<<<BATCH, 128>>>(pH, Wex, Wix, Wei, bo, out);
}